// round 11
// baseline (speedup 1.0000x reference)
#include <cuda_runtime.h>
#include <math.h>
#include <stdint.h>

#define N_SEQ   2048
#define SEQ_LEN 24
#define SEQ_C   9
#define N_FILT  32
#define KM      16
#define HID     128
#define NCLS    10

#define MLP_SEQS 16   // sequences per MLP block -> 128 blocks = single wave

typedef unsigned long long ull;

__device__ ull   g_k2[KM * 4 * N_FILT];   // packed ch-pairs: [i][p][f], p=0..3 -> ch 2p,2p+1
__device__ float g_k8[KM * N_FILT];       // channel 8:       [i][f]
__device__ float g_hkn[KM * N_FILT];      // -0.5*|k_i|^2:    [i][f]
__device__ float g_feats[N_SEQ * N_FILT]; // DTW features

__device__ __forceinline__ ull pack2(float lo, float hi) {
    ull r; asm("mov.b64 %0, {%1, %2};" : "=l"(r) : "f"(lo), "f"(hi)); return r;
}
__device__ __forceinline__ void fma2(ull& d, ull a, ull b) {
    asm("fma.rn.f32x2 %0, %1, %2, %3;" : "=l"(d) : "l"(a), "l"(b), "l"(d));
}
__device__ __forceinline__ void unpack2(ull v, float& lo, float& hi) {
    asm("mov.b64 {%0, %1}, %2;" : "=f"(lo), "=f"(hi) : "l"(v));
}
__device__ __forceinline__ void cp_async16(uint32_t saddr, const void* gptr) {
    asm volatile("cp.async.cg.shared.global [%0], [%1], 16;" :: "r"(saddr), "l"(gptr));
}
__device__ __forceinline__ void cp_async_commit() {
    asm volatile("cp.async.commit_group;");
}
__device__ __forceinline__ void cp_async_wait_all() {
    asm volatile("cp.async.wait_group 0;");
}

// ---------------------------------------------------------------------------
// Kernel 1: build packed transposed kernel arrays + folded norms.
// idx = i*32 + f (512 threads, 1 block) — overhead-dominated, same as before.
// ---------------------------------------------------------------------------
__global__ void prep_kernel(const float* __restrict__ kernels) {
    int idx = blockIdx.x * blockDim.x + threadIdx.x;
    if (idx >= KM * N_FILT) return;
    int i = idx >> 5;
    int f = idx & 31;
    float kv[SEQ_C];
    float nrm = 0.f;
#pragma unroll
    for (int c = 0; c < SEQ_C; ++c) {
        kv[c] = kernels[f * (KM * SEQ_C) + i * SEQ_C + c];
        nrm = fmaf(kv[c], kv[c], nrm);
    }
#pragma unroll
    for (int p = 0; p < 4; ++p)
        g_k2[(i * 4 + p) * N_FILT + f] = pack2(kv[2 * p], kv[2 * p + 1]);
    g_k8[i * N_FILT + f]  = kv[8];
    g_hkn[i * N_FILT + f] = -0.5f * nrm;
}

// ---------------------------------------------------------------------------
// Kernel 2: DTW forward DP. One warp per block/sequence, lane = filter
// (proven-fastest structure), with f32x2-packed dot products:
// per cell 4 FFMA2 + 1 FADD + 2 FFMA on the fma pipe; mins/packs on alu pipe.
// t = <k,s> - (|k|^2+|s|^2)/2  ->  C = -2t ; D = fma(-2, t, best).
// Forward DP == backtracked path-cost sum (exact identity, validated).
// ---------------------------------------------------------------------------
__global__ __launch_bounds__(32) void dtw_kernel(const float* __restrict__ x) {
    __shared__ float2 seq2S[SEQ_LEN][4];   // channel pairs 0..7
    __shared__ float  s8S[SEQ_LEN];        // channel 8
    __shared__ float  hsnS[SEQ_LEN];       // -0.5*|s_j|^2

    const int s = blockIdx.x;
    const int f = threadIdx.x;

    // Stage sequence (216 contiguous floats), packed into channel pairs
    const float* xs = x + s * (SEQ_LEN * SEQ_C);
    for (int i = f; i < SEQ_LEN * SEQ_C; i += 32) {
        int j = i / SEQ_C, c = i - j * SEQ_C;
        float v = xs[i];
        if (c == 8) s8S[j] = v;
        else ((float*)&seq2S[j][c >> 1])[c & 1] = v;
    }
    __syncthreads();

    if (f < SEQ_LEN) {
        float a = 0.f;
#pragma unroll
        for (int p = 0; p < 4; ++p) {
            float2 q = seq2S[f][p];
            a = fmaf(q.x, q.x, a);
            a = fmaf(q.y, q.y, a);
        }
        float v8 = s8S[f];
        a = fmaf(v8, v8, a);
        hsnS[f] = -0.5f * a;
    }
    __syncthreads();

    float Dp[SEQ_LEN];

    // ---- Row 0: cumulative sum of C[0][j] ----
    {
        ull k2[4];
#pragma unroll
        for (int p = 0; p < 4; ++p) k2[p] = g_k2[p * N_FILT + f];
        float k8  = g_k8[f];
        float hkn = g_hkn[f];

        float run = 0.f;
#pragma unroll
        for (int j = 0; j < SEQ_LEN; ++j) {
            ull acc = pack2(hkn, hsnS[j]);
#pragma unroll
            for (int p = 0; p < 4; ++p)
                fma2(acc, k2[p], *reinterpret_cast<const ull*>(&seq2S[j][p]));
            float lo, hi; unpack2(acc, lo, hi);
            float t = fmaf(k8, s8S[j], lo + hi);   // dot - (kn+sn)/2
            run = fmaf(-2.f, t, run);              // run += C
            Dp[j] = run;
        }
    }

    const float INF = __int_as_float(0x7f800000);

    // ---- Rows 1..15 in 3 sweeps of 5 ----
    for (int sw = 0; sw < 3; ++sw) {
        const int i0 = 1 + sw * 5;
        ull   kr2[5][4];
        float kr8[5], hkn[5], left[5];
#pragma unroll
        for (int r = 0; r < 5; ++r) {
#pragma unroll
            for (int p = 0; p < 4; ++p)
                kr2[r][p] = g_k2[((i0 + r) * 4 + p) * N_FILT + f];
            kr8[r] = g_k8[(i0 + r) * N_FILT + f];
            hkn[r] = g_hkn[(i0 + r) * N_FILT + f];
            left[r] = INF;
        }
        float diagc = INF;
#pragma unroll
        for (int j = 0; j < SEQ_LEN; ++j) {
            ull sv[4];
#pragma unroll
            for (int p = 0; p < 4; ++p)
                sv[p] = *reinterpret_cast<const ull*>(&seq2S[j][p]);
            const float s8  = s8S[j];
            const float hsn = hsnS[j];

            float up = Dp[j];
            float oldup = up;
            float diag = diagc;
#pragma unroll
            for (int r = 0; r < 5; ++r) {
                ull acc = pack2(hkn[r], hsn);
                fma2(acc, kr2[r][0], sv[0]);
                fma2(acc, kr2[r][1], sv[1]);
                fma2(acc, kr2[r][2], sv[2]);
                fma2(acc, kr2[r][3], sv[3]);
                float lo, hi; unpack2(acc, lo, hi);
                float t = fmaf(kr8[r], s8, lo + hi);          // dot - (kn+sn)/2
                float best = fminf(left[r], fminf(up, diag)); // alu pipe
                float d = fmaf(-2.f, t, best);                // C + best
                diag = left[r];
                left[r] = d;
                up = d;
            }
            Dp[j] = up;
            diagc = oldup;
        }
    }

    g_feats[s * N_FILT + f] = Dp[SEQ_LEN - 1];
}

// ---------------------------------------------------------------------------
// Kernel 3: MLP, 16 seqs/block -> 128 blocks = one wave. (r10 verbatim, FROZEN)
// ---------------------------------------------------------------------------
__global__ __launch_bounds__(256) void mlp_kernel(
    const float* __restrict__ W1, const float* __restrict__ b1,
    const float* __restrict__ W2, const float* __restrict__ b2,
    const float* __restrict__ Wl, const float* __restrict__ bl,
    float* __restrict__ out) {
    extern __shared__ float smem[];
    float* W2s = smem;                        // [128*128]          64KB
    float* t1S = W2s + HID * HID;             // [h][16]             8KB
    float* t2S = t1S + HID * MLP_SEQS;        // [h][16]             8KB
    float* fSt = t2S + HID * MLP_SEQS;        // [filter][16]        2KB
    float* WlS = fSt + N_FILT * MLP_SEQS;     // [c][h] transposed   5KB

    const int t    = threadIdx.x;
    const int hu   = t & 127;
    const int half = t >> 7;
    const int s0   = blockIdx.x * MLP_SEQS;

    {
        uint32_t base = (uint32_t)__cvta_generic_to_shared(W2s);
        const float4* g = reinterpret_cast<const float4*>(W2);
#pragma unroll
        for (int i = 0; i < 16; ++i) {
            int e = t + i * 256;
            cp_async16(base + e * 16, g + e);
        }
        cp_async_commit();
    }

#pragma unroll
    for (int i = t; i < N_FILT * MLP_SEQS; i += 256) {
        int sq = i >> 5, ff = i & 31;
        fSt[ff * MLP_SEQS + sq] = g_feats[s0 * N_FILT + i];
    }
    for (int i = t; i < HID * NCLS; i += 256) {
        int h = i / NCLS, c = i - h * NCLS;
        WlS[c * HID + h] = Wl[i];
    }
    __syncthreads();

    {
        float b = b1[hu];
        float a0 = b, a1 = b, a2 = b, a3 = b, a4 = b, a5 = b, a6 = b, a7 = b;
#pragma unroll
        for (int ff = 0; ff < N_FILT; ++ff) {
            float w = W1[ff * HID + hu];
            const float4* p = reinterpret_cast<const float4*>(&fSt[ff * MLP_SEQS + half * 8]);
            float4 va = p[0], vb = p[1];
            a0 = fmaf(va.x, w, a0); a1 = fmaf(va.y, w, a1);
            a2 = fmaf(va.z, w, a2); a3 = fmaf(va.w, w, a3);
            a4 = fmaf(vb.x, w, a4); a5 = fmaf(vb.y, w, a5);
            a6 = fmaf(vb.z, w, a6); a7 = fmaf(vb.w, w, a7);
        }
        float4* q = reinterpret_cast<float4*>(&t1S[hu * MLP_SEQS + half * 8]);
        q[0] = make_float4(fmaxf(a0, 0.f), fmaxf(a1, 0.f), fmaxf(a2, 0.f), fmaxf(a3, 0.f));
        q[1] = make_float4(fmaxf(a4, 0.f), fmaxf(a5, 0.f), fmaxf(a6, 0.f), fmaxf(a7, 0.f));
    }
    cp_async_wait_all();
    __syncthreads();

    {
        float c0 = 0.f, c1 = 0.f, c2 = 0.f, c3 = 0.f;
        float c4 = 0.f, c5 = 0.f, c6 = 0.f, c7 = 0.f;
#pragma unroll 16
        for (int h = 0; h < HID; ++h) {
            float w = W2s[h * HID + hu];
            const float4* p = reinterpret_cast<const float4*>(&t1S[h * MLP_SEQS + half * 8]);
            float4 va = p[0], vb = p[1];
            c0 = fmaf(va.x, w, c0); c1 = fmaf(va.y, w, c1);
            c2 = fmaf(va.z, w, c2); c3 = fmaf(va.w, w, c3);
            c4 = fmaf(vb.x, w, c4); c5 = fmaf(vb.y, w, c5);
            c6 = fmaf(vb.z, w, c6); c7 = fmaf(vb.w, w, c7);
        }
        float b = b2[hu];
        float4* q = reinterpret_cast<float4*>(&t2S[hu * MLP_SEQS + half * 8]);
        q[0] = make_float4(fmaxf(c0 + b, 0.f), fmaxf(c1 + b, 0.f),
                           fmaxf(c2 + b, 0.f), fmaxf(c3 + b, 0.f));
        q[1] = make_float4(fmaxf(c4 + b, 0.f), fmaxf(c5 + b, 0.f),
                           fmaxf(c6 + b, 0.f), fmaxf(c7 + b, 0.f));
    }
    __syncthreads();

    const int wid  = t >> 5;
    const int lane = t & 31;
#pragma unroll
    for (int p = 0; p < 2; ++p) {
        const int sq = wid * 2 + p;
        float acc[NCLS];
#pragma unroll
        for (int c = 0; c < NCLS; ++c) acc[c] = 0.f;
#pragma unroll
        for (int q = 0; q < 4; ++q) {
            int h = lane + q * 32;
            float v = t2S[h * MLP_SEQS + sq];
#pragma unroll
            for (int c = 0; c < NCLS; ++c) acc[c] = fmaf(v, WlS[c * HID + h], acc[c]);
        }
#pragma unroll
        for (int off = 16; off > 0; off >>= 1) {
#pragma unroll
            for (int c = 0; c < NCLS; ++c)
                acc[c] += __shfl_xor_sync(0xffffffffu, acc[c], off);
        }
        if (lane == 0) {
            float mx = -__int_as_float(0x7f800000);
#pragma unroll
            for (int c = 0; c < NCLS; ++c) {
                acc[c] += bl[c];
                mx = fmaxf(mx, acc[c]);
            }
            float e[NCLS];
            float sum = 0.f;
#pragma unroll
            for (int c = 0; c < NCLS; ++c) {
                e[c] = __expf(acc[c] - mx);
                sum += e[c];
            }
            float inv = 1.f / sum;
#pragma unroll
            for (int c = 0; c < NCLS; ++c)
                out[(s0 + sq) * NCLS + c] = e[c] * inv;
        }
    }
}

#define MLP_SMEM ((HID * HID + HID * MLP_SEQS + HID * MLP_SEQS + N_FILT * MLP_SEQS + HID * NCLS) * 4)

extern "C" void kernel_launch(void* const* d_in, const int* in_sizes, int n_in,
                              void* d_out, int out_size) {
    const float* x       = (const float*)d_in[0];
    const float* kernels = (const float*)d_in[1];
    const float* W1      = (const float*)d_in[2];
    const float* b1      = (const float*)d_in[3];
    const float* W2      = (const float*)d_in[4];
    const float* b2      = (const float*)d_in[5];
    const float* Wl      = (const float*)d_in[6];
    const float* bl      = (const float*)d_in[7];
    float* out = (float*)d_out;

    cudaFuncSetAttribute(mlp_kernel, cudaFuncAttributeMaxDynamicSharedMemorySize, MLP_SMEM);

    prep_kernel<<<1, 512>>>(kernels);
    dtw_kernel<<<N_SEQ, 32>>>(x);
    mlp_kernel<<<N_SEQ / MLP_SEQS, 256, MLP_SMEM>>>(W1, b1, W2, b2, Wl, bl, out);
}

// round 12
// speedup vs baseline: 1.3080x; 1.3080x over previous
#include <cuda_runtime.h>
#include <math.h>
#include <stdint.h>

#define N_SEQ   2048
#define SEQ_LEN 24
#define SEQ_C   9
#define N_FILT  32
#define KM      16
#define HID     128
#define NCLS    10

#define MLP_SEQS 16   // sequences per MLP block -> 128 blocks = single wave

__device__ float g_kT[KM * SEQ_C * N_FILT];   // kernels transposed: [i][c][f]
__device__ float g_knorm[KM * N_FILT];        // |kernel row|^2:    [i][f]
__device__ float g_feats[N_SEQ * N_FILT];     // DTW features

__device__ __forceinline__ void cp_async16(uint32_t saddr, const void* gptr) {
    asm volatile("cp.async.cg.shared.global [%0], [%1], 16;" :: "r"(saddr), "l"(gptr));
}
__device__ __forceinline__ void cp_async_commit() {
    asm volatile("cp.async.commit_group;");
}
__device__ __forceinline__ void cp_async_wait_all() {
    asm volatile("cp.async.wait_group 0;");
}

// ---------------------------------------------------------------------------
// Kernel 1: transpose kernels to [i][c][f] + row norms.
// Spread over 16 blocks (block = kernel-row i, lane = filter f) so the cold
// DRAM misses are parallel across 16 SMs instead of serialized on one.
// ---------------------------------------------------------------------------
__global__ __launch_bounds__(32) void prep_kernel(const float* __restrict__ kernels) {
    int i = blockIdx.x;        // 0..15
    int f = threadIdx.x;       // 0..31
    float kv[SEQ_C];
    float nrm = 0.f;
#pragma unroll
    for (int c = 0; c < SEQ_C; ++c)
        kv[c] = kernels[f * (KM * SEQ_C) + i * SEQ_C + c];
#pragma unroll
    for (int c = 0; c < SEQ_C; ++c) {
        g_kT[(i * SEQ_C + c) * N_FILT + f] = kv[c];
        nrm = fmaf(kv[c], kv[c], nrm);
    }
    g_knorm[i * N_FILT + f] = nrm;
}

// ---------------------------------------------------------------------------
// Kernel 2: DTW forward DP. One warp per block/sequence, lane = filter.
// (r2 verbatim, FROZEN — measured-fastest across 5 alternative structures)
// ---------------------------------------------------------------------------
__global__ __launch_bounds__(32) void dtw_kernel(const float* __restrict__ x) {
    __shared__ float seqS[SEQ_LEN * SEQ_C];
    __shared__ float snormS[SEQ_LEN];

    const int s = blockIdx.x;
    const int f = threadIdx.x;

    const float* xs = x + s * (SEQ_LEN * SEQ_C);
    for (int t = f; t < SEQ_LEN * SEQ_C; t += 32) seqS[t] = xs[t];
    __syncthreads();

    if (f < SEQ_LEN) {
        float a = 0.f;
#pragma unroll
        for (int c = 0; c < SEQ_C; ++c) {
            float v = seqS[f * SEQ_C + c];
            a = fmaf(v, v, a);
        }
        snormS[f] = a;
    }
    __syncthreads();

    float Dp[SEQ_LEN];

    {
        float k0[SEQ_C];
#pragma unroll
        for (int c = 0; c < SEQ_C; ++c) k0[c] = g_kT[c * N_FILT + f];
        float kn = g_knorm[f];
        float run = 0.f;
#pragma unroll
        for (int j = 0; j < SEQ_LEN; ++j) {
            float dot = 0.f;
#pragma unroll
            for (int c = 0; c < SEQ_C; ++c) dot = fmaf(k0[c], seqS[j * SEQ_C + c], dot);
            float Cv = fmaf(-2.f, dot, kn + snormS[j]);
            run = (j == 0) ? Cv : (run + Cv);
            Dp[j] = run;
        }
    }

    const float INF = __int_as_float(0x7f800000);

    for (int sw = 0; sw < 3; ++sw) {
        const int i0 = 1 + sw * 5;
        float kr[5][SEQ_C], knr[5], left[5];
#pragma unroll
        for (int r = 0; r < 5; ++r) {
#pragma unroll
            for (int c = 0; c < SEQ_C; ++c)
                kr[r][c] = g_kT[((i0 + r) * SEQ_C + c) * N_FILT + f];
            knr[r] = g_knorm[(i0 + r) * N_FILT + f];
            left[r] = INF;
        }
        float diagc = INF;
#pragma unroll
        for (int j = 0; j < SEQ_LEN; ++j) {
            float sv[SEQ_C];
#pragma unroll
            for (int c = 0; c < SEQ_C; ++c) sv[c] = seqS[j * SEQ_C + c];
            float sn = snormS[j];
            float up = Dp[j];
            float oldup = up;
            float diag = diagc;
#pragma unroll
            for (int r = 0; r < 5; ++r) {
                float dot = 0.f;
#pragma unroll
                for (int c = 0; c < SEQ_C; ++c) dot = fmaf(kr[r][c], sv[c], dot);
                float Cv = fmaf(-2.f, dot, knr[r] + sn);
                float best = fminf(left[r], fminf(up, diag));
                float d = Cv + best;
                diag = left[r];
                left[r] = d;
                up = d;
            }
            Dp[j] = up;
            diagc = oldup;
        }
    }

    g_feats[s * N_FILT + f] = Dp[SEQ_LEN - 1];
}

// ---------------------------------------------------------------------------
// Kernel 3: MLP, 16 seqs/block -> 128 blocks = one wave. (r10 verbatim, FROZEN)
// ---------------------------------------------------------------------------
__global__ __launch_bounds__(256) void mlp_kernel(
    const float* __restrict__ W1, const float* __restrict__ b1,
    const float* __restrict__ W2, const float* __restrict__ b2,
    const float* __restrict__ Wl, const float* __restrict__ bl,
    float* __restrict__ out) {
    extern __shared__ float smem[];
    float* W2s = smem;                        // [128*128]          64KB
    float* t1S = W2s + HID * HID;             // [h][16]             8KB
    float* t2S = t1S + HID * MLP_SEQS;        // [h][16]             8KB
    float* fSt = t2S + HID * MLP_SEQS;        // [filter][16]        2KB
    float* WlS = fSt + N_FILT * MLP_SEQS;     // [c][h] transposed   5KB

    const int t    = threadIdx.x;
    const int hu   = t & 127;
    const int half = t >> 7;
    const int s0   = blockIdx.x * MLP_SEQS;

    {
        uint32_t base = (uint32_t)__cvta_generic_to_shared(W2s);
        const float4* g = reinterpret_cast<const float4*>(W2);
#pragma unroll
        for (int i = 0; i < 16; ++i) {
            int e = t + i * 256;
            cp_async16(base + e * 16, g + e);
        }
        cp_async_commit();
    }

#pragma unroll
    for (int i = t; i < N_FILT * MLP_SEQS; i += 256) {
        int sq = i >> 5, ff = i & 31;
        fSt[ff * MLP_SEQS + sq] = g_feats[s0 * N_FILT + i];
    }
    for (int i = t; i < HID * NCLS; i += 256) {
        int h = i / NCLS, c = i - h * NCLS;
        WlS[c * HID + h] = Wl[i];
    }
    __syncthreads();

    {
        float b = b1[hu];
        float a0 = b, a1 = b, a2 = b, a3 = b, a4 = b, a5 = b, a6 = b, a7 = b;
#pragma unroll
        for (int ff = 0; ff < N_FILT; ++ff) {
            float w = W1[ff * HID + hu];
            const float4* p = reinterpret_cast<const float4*>(&fSt[ff * MLP_SEQS + half * 8]);
            float4 va = p[0], vb = p[1];
            a0 = fmaf(va.x, w, a0); a1 = fmaf(va.y, w, a1);
            a2 = fmaf(va.z, w, a2); a3 = fmaf(va.w, w, a3);
            a4 = fmaf(vb.x, w, a4); a5 = fmaf(vb.y, w, a5);
            a6 = fmaf(vb.z, w, a6); a7 = fmaf(vb.w, w, a7);
        }
        float4* q = reinterpret_cast<float4*>(&t1S[hu * MLP_SEQS + half * 8]);
        q[0] = make_float4(fmaxf(a0, 0.f), fmaxf(a1, 0.f), fmaxf(a2, 0.f), fmaxf(a3, 0.f));
        q[1] = make_float4(fmaxf(a4, 0.f), fmaxf(a5, 0.f), fmaxf(a6, 0.f), fmaxf(a7, 0.f));
    }
    cp_async_wait_all();
    __syncthreads();

    {
        float c0 = 0.f, c1 = 0.f, c2 = 0.f, c3 = 0.f;
        float c4 = 0.f, c5 = 0.f, c6 = 0.f, c7 = 0.f;
#pragma unroll 16
        for (int h = 0; h < HID; ++h) {
            float w = W2s[h * HID + hu];
            const float4* p = reinterpret_cast<const float4*>(&t1S[h * MLP_SEQS + half * 8]);
            float4 va = p[0], vb = p[1];
            c0 = fmaf(va.x, w, c0); c1 = fmaf(va.y, w, c1);
            c2 = fmaf(va.z, w, c2); c3 = fmaf(va.w, w, c3);
            c4 = fmaf(vb.x, w, c4); c5 = fmaf(vb.y, w, c5);
            c6 = fmaf(vb.z, w, c6); c7 = fmaf(vb.w, w, c7);
        }
        float b = b2[hu];
        float4* q = reinterpret_cast<float4*>(&t2S[hu * MLP_SEQS + half * 8]);
        q[0] = make_float4(fmaxf(c0 + b, 0.f), fmaxf(c1 + b, 0.f),
                           fmaxf(c2 + b, 0.f), fmaxf(c3 + b, 0.f));
        q[1] = make_float4(fmaxf(c4 + b, 0.f), fmaxf(c5 + b, 0.f),
                           fmaxf(c6 + b, 0.f), fmaxf(c7 + b, 0.f));
    }
    __syncthreads();

    const int wid  = t >> 5;
    const int lane = t & 31;
#pragma unroll
    for (int p = 0; p < 2; ++p) {
        const int sq = wid * 2 + p;
        float acc[NCLS];
#pragma unroll
        for (int c = 0; c < NCLS; ++c) acc[c] = 0.f;
#pragma unroll
        for (int q = 0; q < 4; ++q) {
            int h = lane + q * 32;
            float v = t2S[h * MLP_SEQS + sq];
#pragma unroll
            for (int c = 0; c < NCLS; ++c) acc[c] = fmaf(v, WlS[c * HID + h], acc[c]);
        }
#pragma unroll
        for (int off = 16; off > 0; off >>= 1) {
#pragma unroll
            for (int c = 0; c < NCLS; ++c)
                acc[c] += __shfl_xor_sync(0xffffffffu, acc[c], off);
        }
        if (lane == 0) {
            float mx = -__int_as_float(0x7f800000);
#pragma unroll
            for (int c = 0; c < NCLS; ++c) {
                acc[c] += bl[c];
                mx = fmaxf(mx, acc[c]);
            }
            float e[NCLS];
            float sum = 0.f;
#pragma unroll
            for (int c = 0; c < NCLS; ++c) {
                e[c] = __expf(acc[c] - mx);
                sum += e[c];
            }
            float inv = 1.f / sum;
#pragma unroll
            for (int c = 0; c < NCLS; ++c)
                out[(s0 + sq) * NCLS + c] = e[c] * inv;
        }
    }
}

#define MLP_SMEM ((HID * HID + HID * MLP_SEQS + HID * MLP_SEQS + N_FILT * MLP_SEQS + HID * NCLS) * 4)

extern "C" void kernel_launch(void* const* d_in, const int* in_sizes, int n_in,
                              void* d_out, int out_size) {
    const float* x       = (const float*)d_in[0];
    const float* kernels = (const float*)d_in[1];
    const float* W1      = (const float*)d_in[2];
    const float* b1      = (const float*)d_in[3];
    const float* W2      = (const float*)d_in[4];
    const float* b2      = (const float*)d_in[5];
    const float* Wl      = (const float*)d_in[6];
    const float* bl      = (const float*)d_in[7];
    float* out = (float*)d_out;

    cudaFuncSetAttribute(mlp_kernel, cudaFuncAttributeMaxDynamicSharedMemorySize, MLP_SMEM);

    prep_kernel<<<KM, 32>>>(kernels);
    dtw_kernel<<<N_SEQ, 32>>>(x);
    mlp_kernel<<<N_SEQ / MLP_SEQS, 256, MLP_SMEM>>>(W1, b1, W2, b2, Wl, bl, out);
}

// round 13
// speedup vs baseline: 1.3811x; 1.0559x over previous
#include <cuda_runtime.h>
#include <math.h>
#include <stdint.h>

#define N_SEQ   2048
#define SEQ_LEN 24
#define SEQ_C   9
#define N_FILT  32
#define KM      16
#define HID     128
#define NCLS    10

#define MLP_SEQS 16   // sequences per MLP block -> 128 blocks = single wave

__device__ float g_kT[KM * SEQ_C * N_FILT];   // kernels transposed: [i][c][f]
__device__ float g_knorm[KM * N_FILT];        // |kernel row|^2:    [i][f]
__device__ float g_feats[N_SEQ * N_FILT];     // DTW features

__device__ __forceinline__ void cp_async16(uint32_t saddr, const void* gptr) {
    asm volatile("cp.async.cg.shared.global [%0], [%1], 16;" :: "r"(saddr), "l"(gptr));
}
__device__ __forceinline__ void cp_async_commit() {
    asm volatile("cp.async.commit_group;");
}
__device__ __forceinline__ void cp_async_wait_all() {
    asm volatile("cp.async.wait_group 0;");
}
// PDL: block until the upstream grid (this kernel's programmatic dependency)
// has completed and its memory is visible.
__device__ __forceinline__ void grid_dep_wait() {
    asm volatile("griddepcontrol.wait;" ::: "memory");
}

// ---------------------------------------------------------------------------
// Kernel 1: transpose kernels to [i][c][f] + row norms.
// 16 blocks (block = kernel-row i, lane = filter f). (r12 verbatim)
// ---------------------------------------------------------------------------
__global__ __launch_bounds__(32) void prep_kernel(const float* __restrict__ kernels) {
    int i = blockIdx.x;        // 0..15
    int f = threadIdx.x;       // 0..31
    float kv[SEQ_C];
    float nrm = 0.f;
#pragma unroll
    for (int c = 0; c < SEQ_C; ++c)
        kv[c] = kernels[f * (KM * SEQ_C) + i * SEQ_C + c];
#pragma unroll
    for (int c = 0; c < SEQ_C; ++c) {
        g_kT[(i * SEQ_C + c) * N_FILT + f] = kv[c];
        nrm = fmaf(kv[c], kv[c], nrm);
    }
    g_knorm[i * N_FILT + f] = nrm;
}

// ---------------------------------------------------------------------------
// Kernel 2: DTW forward DP. One warp per block/sequence, lane = filter.
// (r2 inner loop, FROZEN.) PDL: stages sequence + norms (independent of prep
// output) BEFORE griddepcontrol.wait; reads g_kT/g_knorm only after.
// ---------------------------------------------------------------------------
__global__ __launch_bounds__(32) void dtw_kernel(const float* __restrict__ x) {
    __shared__ float seqS[SEQ_LEN * SEQ_C];
    __shared__ float snormS[SEQ_LEN];

    const int s = blockIdx.x;
    const int f = threadIdx.x;

    // Independent of prep output: stage sequence + column norms.
    const float* xs = x + s * (SEQ_LEN * SEQ_C);
    for (int t = f; t < SEQ_LEN * SEQ_C; t += 32) seqS[t] = xs[t];
    __syncthreads();

    if (f < SEQ_LEN) {
        float a = 0.f;
#pragma unroll
        for (int c = 0; c < SEQ_C; ++c) {
            float v = seqS[f * SEQ_C + c];
            a = fmaf(v, v, a);
        }
        snormS[f] = a;
    }
    __syncthreads();

    // Now require prep's g_kT / g_knorm.
    grid_dep_wait();

    float Dp[SEQ_LEN];

    {
        float k0[SEQ_C];
#pragma unroll
        for (int c = 0; c < SEQ_C; ++c) k0[c] = g_kT[c * N_FILT + f];
        float kn = g_knorm[f];
        float run = 0.f;
#pragma unroll
        for (int j = 0; j < SEQ_LEN; ++j) {
            float dot = 0.f;
#pragma unroll
            for (int c = 0; c < SEQ_C; ++c) dot = fmaf(k0[c], seqS[j * SEQ_C + c], dot);
            float Cv = fmaf(-2.f, dot, kn + snormS[j]);
            run = (j == 0) ? Cv : (run + Cv);
            Dp[j] = run;
        }
    }

    const float INF = __int_as_float(0x7f800000);

    for (int sw = 0; sw < 3; ++sw) {
        const int i0 = 1 + sw * 5;
        float kr[5][SEQ_C], knr[5], left[5];
#pragma unroll
        for (int r = 0; r < 5; ++r) {
#pragma unroll
            for (int c = 0; c < SEQ_C; ++c)
                kr[r][c] = g_kT[((i0 + r) * SEQ_C + c) * N_FILT + f];
            knr[r] = g_knorm[(i0 + r) * N_FILT + f];
            left[r] = INF;
        }
        float diagc = INF;
#pragma unroll
        for (int j = 0; j < SEQ_LEN; ++j) {
            float sv[SEQ_C];
#pragma unroll
            for (int c = 0; c < SEQ_C; ++c) sv[c] = seqS[j * SEQ_C + c];
            float sn = snormS[j];
            float up = Dp[j];
            float oldup = up;
            float diag = diagc;
#pragma unroll
            for (int r = 0; r < 5; ++r) {
                float dot = 0.f;
#pragma unroll
                for (int c = 0; c < SEQ_C; ++c) dot = fmaf(kr[r][c], sv[c], dot);
                float Cv = fmaf(-2.f, dot, knr[r] + sn);
                float best = fminf(left[r], fminf(up, diag));
                float d = Cv + best;
                diag = left[r];
                left[r] = d;
                up = d;
            }
            Dp[j] = up;
            diagc = oldup;
        }
    }

    g_feats[s * N_FILT + f] = Dp[SEQ_LEN - 1];
}

// ---------------------------------------------------------------------------
// Kernel 3: MLP, 16 seqs/block -> 128 blocks = one wave. (r10 structure,
// FROZEN.) PDL: W2 cp.async + Wl transpose staged BEFORE griddepcontrol.wait
// (independent of DTW output); g_feats read only after.
// ---------------------------------------------------------------------------
__global__ __launch_bounds__(256) void mlp_kernel(
    const float* __restrict__ W1, const float* __restrict__ b1,
    const float* __restrict__ W2, const float* __restrict__ b2,
    const float* __restrict__ Wl, const float* __restrict__ bl,
    float* __restrict__ out) {
    extern __shared__ float smem[];
    float* W2s = smem;                        // [128*128]          64KB
    float* t1S = W2s + HID * HID;             // [h][16]             8KB
    float* t2S = t1S + HID * MLP_SEQS;        // [h][16]             8KB
    float* fSt = t2S + HID * MLP_SEQS;        // [filter][16]        2KB
    float* WlS = fSt + N_FILT * MLP_SEQS;     // [c][h] transposed   5KB

    const int t    = threadIdx.x;
    const int hu   = t & 127;
    const int half = t >> 7;
    const int s0   = blockIdx.x * MLP_SEQS;

    // Independent of DTW output: prefetch W2, stage Wl transposed.
    {
        uint32_t base = (uint32_t)__cvta_generic_to_shared(W2s);
        const float4* g = reinterpret_cast<const float4*>(W2);
#pragma unroll
        for (int i = 0; i < 16; ++i) {
            int e = t + i * 256;
            cp_async16(base + e * 16, g + e);
        }
        cp_async_commit();
    }
    for (int i = t; i < HID * NCLS; i += 256) {
        int h = i / NCLS, c = i - h * NCLS;
        WlS[c * HID + h] = Wl[i];
    }

    // Now require DTW's g_feats.
    grid_dep_wait();

#pragma unroll
    for (int i = t; i < N_FILT * MLP_SEQS; i += 256) {
        int sq = i >> 5, ff = i & 31;
        fSt[ff * MLP_SEQS + sq] = g_feats[s0 * N_FILT + i];
    }
    __syncthreads();

    {
        float b = b1[hu];
        float a0 = b, a1 = b, a2 = b, a3 = b, a4 = b, a5 = b, a6 = b, a7 = b;
#pragma unroll
        for (int ff = 0; ff < N_FILT; ++ff) {
            float w = W1[ff * HID + hu];
            const float4* p = reinterpret_cast<const float4*>(&fSt[ff * MLP_SEQS + half * 8]);
            float4 va = p[0], vb = p[1];
            a0 = fmaf(va.x, w, a0); a1 = fmaf(va.y, w, a1);
            a2 = fmaf(va.z, w, a2); a3 = fmaf(va.w, w, a3);
            a4 = fmaf(vb.x, w, a4); a5 = fmaf(vb.y, w, a5);
            a6 = fmaf(vb.z, w, a6); a7 = fmaf(vb.w, w, a7);
        }
        float4* q = reinterpret_cast<float4*>(&t1S[hu * MLP_SEQS + half * 8]);
        q[0] = make_float4(fmaxf(a0, 0.f), fmaxf(a1, 0.f), fmaxf(a2, 0.f), fmaxf(a3, 0.f));
        q[1] = make_float4(fmaxf(a4, 0.f), fmaxf(a5, 0.f), fmaxf(a6, 0.f), fmaxf(a7, 0.f));
    }
    cp_async_wait_all();
    __syncthreads();

    {
        float c0 = 0.f, c1 = 0.f, c2 = 0.f, c3 = 0.f;
        float c4 = 0.f, c5 = 0.f, c6 = 0.f, c7 = 0.f;
#pragma unroll 16
        for (int h = 0; h < HID; ++h) {
            float w = W2s[h * HID + hu];
            const float4* p = reinterpret_cast<const float4*>(&t1S[h * MLP_SEQS + half * 8]);
            float4 va = p[0], vb = p[1];
            c0 = fmaf(va.x, w, c0); c1 = fmaf(va.y, w, c1);
            c2 = fmaf(va.z, w, c2); c3 = fmaf(va.w, w, c3);
            c4 = fmaf(vb.x, w, c4); c5 = fmaf(vb.y, w, c5);
            c6 = fmaf(vb.z, w, c6); c7 = fmaf(vb.w, w, c7);
        }
        float b = b2[hu];
        float4* q = reinterpret_cast<float4*>(&t2S[hu * MLP_SEQS + half * 8]);
        q[0] = make_float4(fmaxf(c0 + b, 0.f), fmaxf(c1 + b, 0.f),
                           fmaxf(c2 + b, 0.f), fmaxf(c3 + b, 0.f));
        q[1] = make_float4(fmaxf(c4 + b, 0.f), fmaxf(c5 + b, 0.f),
                           fmaxf(c6 + b, 0.f), fmaxf(c7 + b, 0.f));
    }
    __syncthreads();

    const int wid  = t >> 5;
    const int lane = t & 31;
#pragma unroll
    for (int p = 0; p < 2; ++p) {
        const int sq = wid * 2 + p;
        float acc[NCLS];
#pragma unroll
        for (int c = 0; c < NCLS; ++c) acc[c] = 0.f;
#pragma unroll
        for (int q = 0; q < 4; ++q) {
            int h = lane + q * 32;
            float v = t2S[h * MLP_SEQS + sq];
#pragma unroll
            for (int c = 0; c < NCLS; ++c) acc[c] = fmaf(v, WlS[c * HID + h], acc[c]);
        }
#pragma unroll
        for (int off = 16; off > 0; off >>= 1) {
#pragma unroll
            for (int c = 0; c < NCLS; ++c)
                acc[c] += __shfl_xor_sync(0xffffffffu, acc[c], off);
        }
        if (lane == 0) {
            float mx = -__int_as_float(0x7f800000);
#pragma unroll
            for (int c = 0; c < NCLS; ++c) {
                acc[c] += bl[c];
                mx = fmaxf(mx, acc[c]);
            }
            float e[NCLS];
            float sum = 0.f;
#pragma unroll
            for (int c = 0; c < NCLS; ++c) {
                e[c] = __expf(acc[c] - mx);
                sum += e[c];
            }
            float inv = 1.f / sum;
#pragma unroll
            for (int c = 0; c < NCLS; ++c)
                out[(s0 + sq) * NCLS + c] = e[c] * inv;
        }
    }
}

#define MLP_SMEM ((HID * HID + HID * MLP_SEQS + HID * MLP_SEQS + N_FILT * MLP_SEQS + HID * NCLS) * 4)

extern "C" void kernel_launch(void* const* d_in, const int* in_sizes, int n_in,
                              void* d_out, int out_size) {
    const float* x       = (const float*)d_in[0];
    const float* kernels = (const float*)d_in[1];
    const float* W1      = (const float*)d_in[2];
    const float* b1      = (const float*)d_in[3];
    const float* W2      = (const float*)d_in[4];
    const float* b2      = (const float*)d_in[5];
    const float* Wl      = (const float*)d_in[6];
    const float* bl      = (const float*)d_in[7];
    float* out = (float*)d_out;

    cudaFuncSetAttribute(mlp_kernel, cudaFuncAttributeMaxDynamicSharedMemorySize, MLP_SMEM);

    // Node 1: prep (plain launch).
    prep_kernel<<<KM, 32>>>(kernels);

    // Node 2: DTW, programmatic dependency on prep (overlaps launch+staging).
    {
        cudaLaunchConfig_t cfg = {};
        cfg.gridDim  = dim3(N_SEQ, 1, 1);
        cfg.blockDim = dim3(32, 1, 1);
        cfg.dynamicSmemBytes = 0;
        cfg.stream = 0;
        cudaLaunchAttribute attr[1];
        attr[0].id = cudaLaunchAttributeProgrammaticStreamSerialization;
        attr[0].val.programmaticStreamSerializationAllowed = 1;
        cfg.attrs = attr;
        cfg.numAttrs = 1;
        cudaLaunchKernelEx(&cfg, dtw_kernel, x);
    }

    // Node 3: MLP, programmatic dependency on DTW (overlaps W2 fill).
    {
        cudaLaunchConfig_t cfg = {};
        cfg.gridDim  = dim3(N_SEQ / MLP_SEQS, 1, 1);
        cfg.blockDim = dim3(256, 1, 1);
        cfg.dynamicSmemBytes = MLP_SMEM;
        cfg.stream = 0;
        cudaLaunchAttribute attr[1];
        attr[0].id = cudaLaunchAttributeProgrammaticStreamSerialization;
        attr[0].val.programmaticStreamSerializationAllowed = 1;
        cfg.attrs = attr;
        cfg.numAttrs = 1;
        cudaLaunchKernelEx(&cfg, mlp_kernel, W1, b1, W2, b2, Wl, bl, out);
    }
}